// round 12
// baseline (speedup 1.0000x reference)
#include <cuda_runtime.h>

#define BDIM 4
#define TDIM 300
#define NDIM 200
#define NIN  100
#define KDIM 10
#define NCHUNK 10          // ceil(300/32)

#define BTN (BDIM*TDIM*NDIM)     // 240000
#define OUT_TOTAL (NIN*NDIM + NDIM*NDIM + NDIM*KDIM)  // 62000

#define D1  0.8f
#define D2  0.64f
#define D4  0.4096f
#define D8  0.16777216f
#define D16 0.0281474976710656f
#define D32 0.000792281625142643f

#define MTILES 20          // 5 m-tiles x 4 n-tiles of 64x64
#define KSTEP 25           // k-rows per phase (4 phases per 100-K chunk)
#define AW 132             // duplicated-A smem row width (128 + pad)
#define BW 68              // B smem row width

// scratch (device globals — no cudaMalloc allowed)
__device__ __align__(16) float g_Yr[BTN];                  // revfilter(G2)
__device__ __align__(16) float g_e1f[BDIM * TDIM * KDIM];  // revfilter(e1)

typedef unsigned long long ull;

__device__ __forceinline__ void fma2(ull& d, ull a, ull b) {
    asm("fma.rn.f32x2 %0, %1, %2, %3;" : "=l"(d) : "l"(a), "l"(b), "l"(d));
}
__device__ __forceinline__ float2 upk(ull v) {
    unsigned lo, hi;
    asm("mov.b64 {%0, %1}, %2;" : "=r"(lo), "=r"(hi) : "l"(v));
    float2 f;
    f.x = __uint_as_float(lo);
    f.y = __uint_as_float(hi);
    return f;
}

__device__ __forceinline__ float dpow_lane(int l) {
    float p = 1.f;
    if (l & 1)  p *= D1;
    if (l & 2)  p *= D2;
    if (l & 4)  p *= D4;
    if (l & 8)  p *= D8;
    if (l & 16) p *= D16;
    return p;
}

__device__ __forceinline__ float warp_rscan(float a, int lane) {
    float tmp;
    tmp = __shfl_down_sync(0xffffffffu, a, 1);  if (lane < 31) a = fmaf(tmp, D1,  a);
    tmp = __shfl_down_sync(0xffffffffu, a, 2);  if (lane < 30) a = fmaf(tmp, D2,  a);
    tmp = __shfl_down_sync(0xffffffffu, a, 4);  if (lane < 28) a = fmaf(tmp, D4,  a);
    tmp = __shfl_down_sync(0xffffffffu, a, 8);  if (lane < 24) a = fmaf(tmp, D8,  a);
    tmp = __shfl_down_sync(0xffffffffu, a, 16); if (lane < 16) a = fmaf(tmp, D16, a);
    return a;
}

// ---------------------------------------------------------------------------
// Kernel 1: G2 + reverse filter -> Yr; e1f; zero d_out.
// ---------------------------------------------------------------------------
__global__ void __launch_bounds__(512) k_g2(
        const float* __restrict__ v, const float* __restrict__ z,
        const float* __restrict__ e1, const float* __restrict__ e2,
        const float* __restrict__ w_out, float* __restrict__ out) {
    __shared__ float s_z[160][17];          // 5 chunks of 32 t x 16 lanes
    __shared__ float s_v[160][17];
    __shared__ float s_e1[TDIM * KDIM];     // [t][k]
    __shared__ float s_e1T[KDIM * 304];     // filtered, [k][t]
    __shared__ float s_w[16 * KDIM];

    const int tid  = threadIdx.x;
    const int lane = tid & 31;
    const int wrp  = tid >> 5;     // 0..15 (owns one neuron)
    const int tt   = tid >> 4;     // 0..31 (t within chunk, load layout)
    const int nn   = tid & 15;     // 0..15 (lane col, load layout)
    const int bx   = blockIdx.x;

    const float dl  = dpow_lane(lane);
    const float drl = D32 / dl;    // d^(32-lane)

    if (bx < 52) {
        const int b  = bx / 13;
        const int nt = bx % 13;
        const int n0 = nt * 16;
        const int n_ld = n0 + nn;

        for (int i = tid; i < TDIM * KDIM; i += 512)
            s_e1[i] = e1[b * TDIM * KDIM + i];
        if (tid < 16 * KDIM) {
            int n = n0 + tid / KDIM;
            s_w[tid] = (n < NDIM) ? w_out[n * KDIM + tid % KDIM] : 0.f;
        }

        const int  n_w = n0 + wrp;
        const float c2 = (n_w < NDIM) ? 0.25f * e2[n_w] : 0.f;  // REG/(B*T)

        // prefetch z/v group 0 (load layout)
        float zr[5], vr[5];
        #pragma unroll
        for (int c = 0; c < 5; c++) {
            int t_ld = c * 32 + tt;
            bool ok = (t_ld < TDIM) && (n_ld < NDIM);
            int off = (b * TDIM + t_ld) * NDIM + n_ld;
            zr[c] = ok ? z[off] : 0.f;
            vr[c] = ok ? v[off] : 0.6f;
        }
        __syncthreads();   // s_e1 ready

        // --- e1f = revfilter(e1) per channel (warps 0..9) ---
        if (wrp < KDIM) {
            float ef[NCHUNK], l0[NCHUNK];
            #pragma unroll
            for (int c = 0; c < NCHUNK; c++) {
                int t = c * 32 + lane;
                float xv = (t < TDIM) ? s_e1[t * KDIM + wrp] : 0.f;
                ef[c] = warp_rscan(xv, lane);
            }
            #pragma unroll
            for (int c = 0; c < NCHUNK; c++)
                l0[c] = __shfl_sync(0xffffffffu, ef[c], 0);
            float carry = 0.f;
            #pragma unroll
            for (int c = NCHUNK - 1; c >= 0; c--) {
                float full = fmaf(carry, drl, ef[c]);
                carry = fmaf(carry, D32, l0[c]);
                int t = c * 32 + lane;
                if (t < TDIM) {
                    s_e1T[wrp * 304 + t] = full;
                    if (nt == 0)
                        g_e1f[(b * TDIM + t) * KDIM + wrp] = full;
                }
            }
        }

        // --- z/v staging; post, Lf, G2 per chunk ---
        float g2r[NCHUNK];
        unsigned pm = 0u;
        float wv[KDIM];
        #pragma unroll
        for (int g = 0; g < 2; g++) {
            if (g == 1) {
                #pragma unroll
                for (int c = 0; c < 5; c++) {
                    int t_ld = (5 + c) * 32 + tt;
                    bool ok = (t_ld < TDIM) && (n_ld < NDIM);
                    int off = (b * TDIM + t_ld) * NDIM + n_ld;
                    zr[c] = ok ? z[off] : 0.f;
                    vr[c] = ok ? v[off] : 0.6f;
                }
                __syncthreads();   // group0 consumed
            }
            #pragma unroll
            for (int c = 0; c < 5; c++) {
                s_z[c * 32 + tt][nn] = zr[c];
                s_v[c * 32 + tt][nn] = vr[c];
            }
            __syncthreads();       // staging + (g==0) s_e1T visible
            if (g == 0) {
                #pragma unroll
                for (int k = 0; k < KDIM; k++) wv[k] = s_w[wrp * KDIM + k];
            }
            #pragma unroll
            for (int cc = 0; cc < 5; cc++) {
                const int c = g * 5 + cc;
                const float zt = s_z[cc * 32 + lane][wrp];
                const float vt = s_v[cc * 32 + lane][wrp];
                const unsigned m = __ballot_sync(0xffffffffu, zt > 0.f);
                const ull w64 = ((ull)m << 32) | (ull)pm;
                const bool refract = ((w64 >> (28 + lane)) & 0xFull) != 0ull;
                pm = m;
                const float vs = (vt - 0.6f) * (1.0f / 0.6f);
                const float post = refract ? 0.f : 0.5f * fmaxf(1.0f - fabsf(vs), 0.0f);

                const int t = c * 32 + lane;
                float Ls = 0.f;
                if (t < TDIM) {
                    #pragma unroll
                    for (int k = 0; k < KDIM; k++)
                        Ls = fmaf(s_e1T[k * 304 + t], wv[k], Ls);
                    g2r[c] = post * (Ls + c2);
                } else {
                    g2r[c] = 0.f;
                }
            }
        }

        // --- reverse scan of G2 -> Yr (chunk-local rscans + scalar carry) ---
        {
            float l0[NCHUNK];
            #pragma unroll
            for (int c = 0; c < NCHUNK; c++)
                g2r[c] = warp_rscan(g2r[c], lane);
            #pragma unroll
            for (int c = 0; c < NCHUNK; c++)
                l0[c] = __shfl_sync(0xffffffffu, g2r[c], 0);
            float carry = 0.f;
            #pragma unroll
            for (int c = NCHUNK - 1; c >= 0; c--) {
                g2r[c] = fmaf(carry, drl, g2r[c]);
                carry = fmaf(carry, D32, l0[c]);
            }
        }

        // --- stage + coalesced store of Yr, two groups ---
        #pragma unroll
        for (int g = 0; g < 2; g++) {
            __syncthreads();
            #pragma unroll
            for (int cc = 0; cc < 5; cc++)
                s_z[cc * 32 + lane][wrp] = g2r[g * 5 + cc];
            __syncthreads();
            #pragma unroll
            for (int cc = 0; cc < 5; cc++) {
                int t_st = (g * 5 + cc) * 32 + tt;
                if (t_st < TDIM && n_ld < NDIM)
                    g_Yr[(b * TDIM + t_st) * NDIM + n_ld] = s_z[cc * 32 + tt][nn];
            }
        }
    } else {
        // zero the output (k_gemm atomically accumulates into it)
        float4 zv = make_float4(0.f, 0.f, 0.f, 0.f);
        for (int i = (bx - 52) * 512 + tid; i < OUT_TOTAL / 4; i += 4 * 512)
            ((float4*)out)[i] = zv;
    }
}

// ---------------------------------------------------------------------------
// Kernel 2: split-K GEMMs, register-staged double-buffered, duplicated-A smem
// (FFMA2 inner loop with zero pack-MOVs), atomicAdd into pre-zeroed d_out.
//  grid (24, 12): x<20 main 64x64 tiles of [x; z_prev]^T x Yr,
//                 x>=20 dw_out 64x16 tiles of z^T x e1f.
//  y = K-chunk of 100: b = y/3, t0 = (y%3)*100. 4 phases of 25 k-rows.
// ---------------------------------------------------------------------------
__global__ void __launch_bounds__(256, 4) k_gemm(
        const float* __restrict__ x, const float* __restrict__ z,
        float* __restrict__ out) {
    __shared__ float As[2][KSTEP][AW];   // duplicated pairs: 2*25*132*4 = 26.4KB
    __shared__ float Bs[2][KSTEP][BW];   // 13.6KB

    const int chunk = blockIdx.y;
    const int b  = chunk / 3;
    const int t0 = (chunk % 3) * 100;
    const int tile = blockIdx.x;
    const int tid  = threadIdx.x;
    const int ty = tid >> 4, tx = tid & 15;
    const int bt0 = b * TDIM + t0;

    if (tile < MTILES) {
        const int m0 = (tile / 4) * 64;
        const int n0 = (tile % 4) * 64;

        ull acc[4][2];
        #pragma unroll
        for (int i = 0; i < 4; i++) { acc[i][0] = 0ull; acc[i][1] = 0ull; }

        // per-thread staging registers (2 float4 per operand per phase)
        float4 ra[2], rb[2];

        // prefetch phase 0
        #pragma unroll
        for (int r = 0; r < 2; r++) {
            int idx = tid + r * 256;
            float4 a = make_float4(0.f, 0.f, 0.f, 0.f);
            float4 bb = make_float4(0.f, 0.f, 0.f, 0.f);
            if (idx < KSTEP * 16) {
                int kk = idx >> 4, mm4 = (idx & 15) << 2;
                int t_local = t0 + kk;
                int trow = b * TDIM + t_local;
                int gm = m0 + mm4;
                if (gm < NIN)
                    a = *(const float4*)&x[trow * NIN + gm];
                else if (gm < NIN + NDIM && t_local > 0)
                    a = *(const float4*)&z[(trow - 1) * NDIM + (gm - NIN)];
                int gn = n0 + mm4;
                if (gn < NDIM)
                    bb = *(const float4*)&g_Yr[trow * NDIM + gn];
            }
            ra[r] = a; rb[r] = bb;
        }

        #pragma unroll
        for (int p = 0; p < 4; p++) {
            const int buf = p & 1;
            // land staged regs into smem (A duplicated: (a,a) pairs)
            #pragma unroll
            for (int r = 0; r < 2; r++) {
                int idx = tid + r * 256;
                if (idx < KSTEP * 16) {
                    int kk = idx >> 4, mm = idx & 15;
                    float4 a = ra[r];
                    *(float4*)&As[buf][kk][mm * 8]     = make_float4(a.x, a.x, a.y, a.y);
                    *(float4*)&As[buf][kk][mm * 8 + 4] = make_float4(a.z, a.z, a.w, a.w);
                    *(float4*)&Bs[buf][kk][mm * 4]     = rb[r];
                }
            }
            __syncthreads();
            // issue next phase's loads (latency overlapped with compute below)
            if (p < 3) {
                #pragma unroll
                for (int r = 0; r < 2; r++) {
                    int idx = tid + r * 256;
                    float4 a = make_float4(0.f, 0.f, 0.f, 0.f);
                    float4 bb = make_float4(0.f, 0.f, 0.f, 0.f);
                    if (idx < KSTEP * 16) {
                        int kk = idx >> 4, mm4 = (idx & 15) << 2;
                        int t_local = t0 + (p + 1) * KSTEP + kk;
                        int trow = b * TDIM + t_local;
                        int gm = m0 + mm4;
                        if (gm < NIN)
                            a = *(const float4*)&x[trow * NIN + gm];
                        else if (gm < NIN + NDIM && t_local > 0)
                            a = *(const float4*)&z[(trow - 1) * NDIM + (gm - NIN)];
                        int gn = n0 + mm4;
                        if (gn < NDIM)
                            bb = *(const float4*)&g_Yr[trow * NDIM + gn];
                    }
                    ra[r] = a; rb[r] = bb;
                }
            }
            // compute on current buffer: 3 LDS.128 + 8 FFMA2 per k, no MOVs
            #pragma unroll
            for (int kk = 0; kk < KSTEP; kk++) {
                ulonglong2 a01 = *(const ulonglong2*)&As[buf][kk][ty * 8];
                ulonglong2 a23 = *(const ulonglong2*)&As[buf][kk][ty * 8 + 4];
                ulonglong2 bv  = *(const ulonglong2*)&Bs[buf][kk][tx * 4];
                fma2(acc[0][0], a01.x, bv.x); fma2(acc[0][1], a01.x, bv.y);
                fma2(acc[1][0], a01.y, bv.x); fma2(acc[1][1], a01.y, bv.y);
                fma2(acc[2][0], a23.x, bv.x); fma2(acc[2][1], a23.x, bv.y);
                fma2(acc[3][0], a23.y, bv.x); fma2(acc[3][1], a23.y, bv.y);
            }
            __syncthreads();
        }

        #pragma unroll
        for (int i = 0; i < 4; i++) {
            float2 p0 = upk(acc[i][0]);
            float2 p1 = upk(acc[i][1]);
            float vals[4] = {p0.x, p0.y, p1.x, p1.y};
            int gm = m0 + ty * 4 + i;
            #pragma unroll
            for (int j = 0; j < 4; j++) {
                int gn = n0 + tx * 4 + j;
                if (gn < NDIM) {
                    if (gm < NIN) {
                        atomicAdd(&out[gm * NDIM + gn], vals[j]);
                    } else if (gm < NIN + NDIM) {
                        int rr = gm - NIN;
                        if (rr != gn)  // autapse mask: diagonal stays 0
                            atomicAdd(&out[NIN * NDIM + rr * NDIM + gn], vals[j]);
                    }
                }
            }
        }
    } else {
        // dw_out tile: 64 m-rows (neurons) x 10 cols; A=z (float4), B=e1f
        const int m0 = (tile - MTILES) * 64;
        float acc[4] = {0.f, 0.f, 0.f, 0.f};

        // preload e1f for all 100 k-rows: 1000 contiguous floats -> Bs flat
        float* sB = &Bs[0][0][0];
        if (tid < 250)
            ((float4*)sB)[tid] = ((const float4*)&g_e1f[bt0 * KDIM])[tid];

        float4 ra[2];
        #pragma unroll
        for (int r = 0; r < 2; r++) {
            int idx = tid + r * 256;
            float4 a = make_float4(0.f, 0.f, 0.f, 0.f);
            if (idx < KSTEP * 16) {
                int kk = idx >> 4, mm4 = (idx & 15) << 2;
                int gm = m0 + mm4;
                if (gm < NDIM)
                    a = *(const float4*)&z[(bt0 + kk) * NDIM + gm];
            }
            ra[r] = a;
        }

        #pragma unroll
        for (int p = 0; p < 4; p++) {
            const int buf = p & 1;
            #pragma unroll
            for (int r = 0; r < 2; r++) {
                int idx = tid + r * 256;
                if (idx < KSTEP * 16) {
                    int kk = idx >> 4, mm4 = (idx & 15) << 2;
                    *(float4*)&As[buf][kk][mm4] = ra[r];
                }
            }
            __syncthreads();
            if (p < 3) {
                #pragma unroll
                for (int r = 0; r < 2; r++) {
                    int idx = tid + r * 256;
                    float4 a = make_float4(0.f, 0.f, 0.f, 0.f);
                    if (idx < KSTEP * 16) {
                        int kk = idx >> 4, mm4 = (idx & 15) << 2;
                        int gm = m0 + mm4;
                        if (gm < NDIM)
                            a = *(const float4*)&z[(bt0 + (p + 1) * KSTEP + kk) * NDIM + gm];
                    }
                    ra[r] = a;
                }
            }
            #pragma unroll
            for (int kk = 0; kk < KSTEP; kk++) {
                float4 av = *(const float4*)&As[buf][kk][ty * 4];
                float bb = sB[(p * KSTEP + kk) * KDIM + tx];  // tx>=10 garbage, unused
                acc[0] = fmaf(av.x, bb, acc[0]);
                acc[1] = fmaf(av.y, bb, acc[1]);
                acc[2] = fmaf(av.z, bb, acc[2]);
                acc[3] = fmaf(av.w, bb, acc[3]);
            }
            __syncthreads();
        }

        if (tx < KDIM) {
            #pragma unroll
            for (int i = 0; i < 4; i++) {
                int gm = m0 + ty * 4 + i;
                if (gm < NDIM)
                    atomicAdd(&out[NIN * NDIM + NDIM * NDIM + gm * KDIM + tx], acc[i]);
            }
        }
    }
}

extern "C" void kernel_launch(void* const* d_in, const int* in_sizes, int n_in,
                              void* d_out, int out_size) {
    const float* v     = (const float*)d_in[0];
    const float* z     = (const float*)d_in[1];
    const float* x     = (const float*)d_in[2];
    const float* e1    = (const float*)d_in[3];
    const float* e2    = (const float*)d_in[4];
    const float* w_out = (const float*)d_in[5];
    float* out = (float*)d_out;

    k_g2<<<56, 512>>>(v, z, e1, e2, w_out, out);
    k_gemm<<<dim3(24, 12), 256>>>(x, z, out);
}

// round 14
// speedup vs baseline: 1.2120x; 1.2120x over previous
#include <cuda_runtime.h>

#define BDIM 4
#define TDIM 300
#define NDIM 200
#define NIN  100
#define KDIM 10

#define BTN (BDIM*TDIM*NDIM)     // 240000
#define OUT_TOTAL (NIN*NDIM + NDIM*NDIM + NDIM*KDIM)  // 62000

#define D1  0.8f
#define D2  0.64f
#define D4  0.4096f
#define D8  0.16777216f
#define D16 0.0281474976710656f
#define D32 0.000792281625142643f

#define MTILES 20          // 5 m-tiles x 4 n-tiles of 64x64
#define KSTEP 25           // k-rows per phase (4 phases per 100-K chunk)

// scratch (device globals — no cudaMalloc allowed)
__device__ __align__(16) float g_Yr[BTN];                  // revfilter(G2)
__device__ __align__(16) float g_e1f[BDIM * TDIM * KDIM];  // revfilter(e1)

typedef unsigned long long ull;

__device__ __forceinline__ ull pk(float x, float y) {
    ull r;
    asm("mov.b64 %0, {%1, %2};" : "=l"(r)
        : "r"(__float_as_uint(x)), "r"(__float_as_uint(y)));
    return r;
}
__device__ __forceinline__ void fma2(ull& d, ull a, ull b) {
    asm("fma.rn.f32x2 %0, %1, %2, %3;" : "=l"(d) : "l"(a), "l"(b), "l"(d));
}
__device__ __forceinline__ float2 upk(ull v) {
    unsigned lo, hi;
    asm("mov.b64 {%0, %1}, %2;" : "=r"(lo), "=r"(hi) : "l"(v));
    float2 f;
    f.x = __uint_as_float(lo);
    f.y = __uint_as_float(hi);
    return f;
}

__device__ __forceinline__ float dpow_lane(int l) {
    float p = 1.f;
    if (l & 1)  p *= D1;
    if (l & 2)  p *= D2;
    if (l & 4)  p *= D4;
    if (l & 8)  p *= D8;
    if (l & 16) p *= D16;
    return p;
}

__device__ __forceinline__ float warp_rscan(float a, int lane) {
    float tmp;
    tmp = __shfl_down_sync(0xffffffffu, a, 1);  if (lane < 31) a = fmaf(tmp, D1,  a);
    tmp = __shfl_down_sync(0xffffffffu, a, 2);  if (lane < 30) a = fmaf(tmp, D2,  a);
    tmp = __shfl_down_sync(0xffffffffu, a, 4);  if (lane < 28) a = fmaf(tmp, D4,  a);
    tmp = __shfl_down_sync(0xffffffffu, a, 8);  if (lane < 24) a = fmaf(tmp, D8,  a);
    tmp = __shfl_down_sync(0xffffffffu, a, 16); if (lane < 16) a = fmaf(tmp, D16, a);
    return a;
}

// ---------------------------------------------------------------------------
// Kernel 1: G2 + reverse filter -> Yr (split-T, 2 warps per neuron); e1f in
// dedicated blocks; zero d_out in dedicated blocks.
//  blocks  0..99  : (b, 8-neuron tile), 16 warps = 8 neurons x 2 T-halves.
//  blocks 100..103: e1f = revfilter(e1) for batch b = bx-100.
//  blocks 104..105: zero d_out.
// ---------------------------------------------------------------------------
__global__ void __launch_bounds__(512) k_g2(
        const float* __restrict__ v, const float* __restrict__ z,
        const float* __restrict__ e1, const float* __restrict__ e2,
        const float* __restrict__ w_out, float* __restrict__ out) {
    __shared__ float s_z[8][304];
    __shared__ float s_v[8][304];
    __shared__ float s_et[10][304];    // e1 transposed [k][t] (G2 blocks)
                                       // or flat e1 [t*10+k] (e1f blocks)
    __shared__ float s_c[2][8];        // cross-half carries: [0]=Lf160 [1]=Yr160

    const int tid  = threadIdx.x;
    const int lane = tid & 31;
    const int wrp  = tid >> 5;         // 0..15
    const int bx   = blockIdx.x;

    const float dl  = dpow_lane(lane);
    const float drl = D32 / dl;        // d^(32-lane)

    if (bx < 100) {
        const int b  = bx / 25;
        const int n0 = (bx % 25) * 8;          // 25*8 = 200 exact, no ragged n
        const int nrn  = wrp >> 1;             // 0..7
        const int half = wrp & 1;              // 0 = t<160, 1 = t>=160
        const int n    = n0 + nrn;

        const float c2 = 0.25f * e2[n];        // REG/(B*T)
        float wv[KDIM];
        #pragma unroll
        for (int k = 0; k < KDIM; k++) wv[k] = w_out[n * KDIM + k];

        // ---- stage z, v (8 n x 300 t) and e1 transposed ----
        for (int idx = tid; idx < 2400; idx += 512) {
            int t = idx >> 3, j = idx & 7;
            int off = (b * TDIM + t) * NDIM + n0 + j;
            s_z[j][t] = z[off];
            s_v[j][t] = v[off];
        }
        if (tid < 32) {                // pad t = 300..303
            int j = tid >> 2, t = 300 + (tid & 3);
            s_z[j][t] = 0.f;
            s_v[j][t] = 0.6f;
        }
        for (int idx = tid; idx < TDIM * KDIM; idx += 512) {
            int t = idx / KDIM, k = idx % KDIM;
            s_et[k][t] = e1[b * TDIM * KDIM + idx];
        }
        if (tid < 40) {                // pad e1T t = 300..303
            int k = tid % KDIM, t = 300 + tid / KDIM;
            s_et[k][t] = 0.f;
        }
        __syncthreads();               // S1

        // ---- per-chunk: post (ballot window) + L (gemv) ----
        float Lr[5], post[5];
        unsigned pm;
        if (half == 0) {
            pm = 0u;
        } else {
            float zp = s_z[nrn][4 * 32 + lane];          // chunk 4 (t 128..159)
            pm = __ballot_sync(0xffffffffu, zp > 0.f);
        }
        #pragma unroll
        for (int cc = 0; cc < 5; cc++) {
            const int t = (half * 5 + cc) * 32 + lane;   // <= 319; smem padded to 304?
            const int ts = (t < 304) ? t : 303;          // safe smem read index
            const float zt = (t < 304) ? s_z[nrn][t] : 0.f;
            const float vt = s_v[nrn][ts];
            const unsigned m = __ballot_sync(0xffffffffu, zt > 0.f);
            const ull w64 = ((ull)m << 32) | (ull)pm;
            const bool refract = ((w64 >> (28 + lane)) & 0xFull) != 0ull;
            pm = m;
            const float vs = (vt - 0.6f) * (1.0f / 0.6f);
            post[cc] = (refract || t >= TDIM)
                     ? 0.f : 0.5f * fmaxf(1.0f - fabsf(vs), 0.0f);
            float Ls = 0.f;
            #pragma unroll
            for (int k = 0; k < KDIM; k++)
                Ls = fmaf(s_et[k][ts], wv[k], Ls);
            Lr[cc] = (t < TDIM) ? Ls : 0.f;
        }

        // ---- Lf = revfilter(L): local rscans + split-half carry ----
        float lf[5], l0[5];
        #pragma unroll
        for (int cc = 0; cc < 5; cc++) {
            lf[cc] = warp_rscan(Lr[cc], lane);
            l0[cc] = __shfl_sync(0xffffffffu, lf[cc], 0);
        }
        if (half == 1) {
            float carry = 0.f;
            #pragma unroll
            for (int cc = 4; cc >= 0; cc--) {
                lf[cc] = fmaf(carry, drl, lf[cc]);
                carry  = fmaf(carry, D32, l0[cc]);
            }
            if (lane == 0) s_c[0][nrn] = carry;          // = Lf(160)
        }
        __syncthreads();               // S2
        if (half == 0) {
            float carry = s_c[0][nrn];
            #pragma unroll
            for (int cc = 4; cc >= 0; cc--) {
                lf[cc] = fmaf(carry, drl, lf[cc]);
                carry  = fmaf(carry, D32, l0[cc]);
            }
        }

        // ---- G2 = post*(Lf + c2); Yr = revfilter(G2) same split scheme ----
        float yr[5];
        #pragma unroll
        for (int cc = 0; cc < 5; cc++) {
            float g2 = post[cc] * (lf[cc] + c2);         // post==0 for t>=300
            yr[cc] = warp_rscan(g2, lane);
            l0[cc] = __shfl_sync(0xffffffffu, yr[cc], 0);
        }
        if (half == 1) {
            float carry = 0.f;
            #pragma unroll
            for (int cc = 4; cc >= 0; cc--) {
                yr[cc] = fmaf(carry, drl, yr[cc]);
                carry  = fmaf(carry, D32, l0[cc]);
            }
            if (lane == 0) s_c[1][nrn] = carry;          // = Yr(160)
        }
        __syncthreads();               // S3
        if (half == 0) {
            float carry = s_c[1][nrn];
            #pragma unroll
            for (int cc = 4; cc >= 0; cc--) {
                yr[cc] = fmaf(carry, drl, yr[cc]);
                carry  = fmaf(carry, D32, l0[cc]);
            }
        }

        // ---- stage Yr (z tile reuse) + cooperative store ----
        // R13 BUG FIX: chunk 9 reaches t=319 > 303 and overflowed into the
        // next neuron's row. Guard to t < TDIM (t>=300 never stored anyway).
        #pragma unroll
        for (int cc = 0; cc < 5; cc++) {
            int t = (half * 5 + cc) * 32 + lane;
            if (t < TDIM)
                s_z[nrn][t] = yr[cc];
        }
        __syncthreads();               // S4
        for (int idx = tid; idx < 2400; idx += 512) {
            int t = idx >> 3, j = idx & 7;
            g_Yr[(b * TDIM + t) * NDIM + n0 + j] = s_z[j][t];
        }
    } else if (bx < 104) {
        // ---- e1f = revfilter(e1) for batch b, channels 0..9 (warps 0..9) ----
        const int b = bx - 100;
        float* sE = &s_et[0][0];       // flat [t*10+k], 3040 >= 3000
        for (int i = tid; i < TDIM * KDIM; i += 512)
            sE[i] = e1[b * TDIM * KDIM + i];
        __syncthreads();
        if (wrp < KDIM) {
            float ef[10], l0v[10];
            #pragma unroll
            for (int c = 0; c < 10; c++) {
                int t = c * 32 + lane;
                float xv = (t < TDIM) ? sE[t * KDIM + wrp] : 0.f;
                ef[c] = warp_rscan(xv, lane);
            }
            #pragma unroll
            for (int c = 0; c < 10; c++)
                l0v[c] = __shfl_sync(0xffffffffu, ef[c], 0);
            float carry = 0.f;
            #pragma unroll
            for (int c = 9; c >= 0; c--) {
                float full = fmaf(carry, drl, ef[c]);
                carry = fmaf(carry, D32, l0v[c]);
                int t = c * 32 + lane;
                if (t < TDIM)
                    g_e1f[(b * TDIM + t) * KDIM + wrp] = full;
            }
        }
    } else {
        // ---- zero d_out (k_gemm atomically accumulates) ----
        float4 zv = make_float4(0.f, 0.f, 0.f, 0.f);
        for (int i = (bx - 104) * 512 + tid; i < OUT_TOTAL / 4; i += 2 * 512)
            ((float4*)out)[i] = zv;
    }
}

// ---------------------------------------------------------------------------
// Kernel 2: split-K GEMMs, register-staged double-buffered, float4 I/O,
// atomicAdd into pre-zeroed d_out. (EXACT R9 version; measured 12.6us)
//  grid (24, 12): x<20 main 64x64 tiles of [x; z_prev]^T x Yr,
//                 x>=20 dw_out 64x16 tiles of z^T x e1f.
//  y = K-chunk of 100: b = y/3, t0 = (y%3)*100. 4 phases of 25 k-rows.
// ---------------------------------------------------------------------------
__global__ void __launch_bounds__(256) k_gemm(
        const float* __restrict__ x, const float* __restrict__ z,
        float* __restrict__ out) {
    __shared__ float As[2][KSTEP][68];
    __shared__ float Bs[2][KSTEP][68];

    const int chunk = blockIdx.y;
    const int b  = chunk / 3;
    const int t0 = (chunk % 3) * 100;
    const int tile = blockIdx.x;
    const int tid  = threadIdx.x;
    const int ty = tid >> 4, tx = tid & 15;
    const int bt0 = b * TDIM + t0;

    if (tile < MTILES) {
        const int m0 = (tile / 4) * 64;
        const int n0 = (tile % 4) * 64;

        ull acc[4][2];
        #pragma unroll
        for (int i = 0; i < 4; i++) { acc[i][0] = 0ull; acc[i][1] = 0ull; }

        float4 ra[2], rb[2];

        // prefetch phase 0
        #pragma unroll
        for (int r = 0; r < 2; r++) {
            int idx = tid + r * 256;
            float4 a = make_float4(0.f, 0.f, 0.f, 0.f);
            float4 bb = make_float4(0.f, 0.f, 0.f, 0.f);
            if (idx < KSTEP * 16) {
                int kk = idx >> 4, mm4 = (idx & 15) << 2;
                int t_local = t0 + kk;
                int trow = b * TDIM + t_local;
                int gm = m0 + mm4;
                if (gm < NIN)
                    a = *(const float4*)&x[trow * NIN + gm];
                else if (gm < NIN + NDIM && t_local > 0)
                    a = *(const float4*)&z[(trow - 1) * NDIM + (gm - NIN)];
                int gn = n0 + mm4;
                if (gn < NDIM)
                    bb = *(const float4*)&g_Yr[trow * NDIM + gn];
            }
            ra[r] = a; rb[r] = bb;
        }

        #pragma unroll
        for (int p = 0; p < 4; p++) {
            const int buf = p & 1;
            #pragma unroll
            for (int r = 0; r < 2; r++) {
                int idx = tid + r * 256;
                if (idx < KSTEP * 16) {
                    int kk = idx >> 4, mm4 = (idx & 15) << 2;
                    *(float4*)&As[buf][kk][mm4] = ra[r];
                    *(float4*)&Bs[buf][kk][mm4] = rb[r];
                }
            }
            __syncthreads();
            if (p < 3) {
                #pragma unroll
                for (int r = 0; r < 2; r++) {
                    int idx = tid + r * 256;
                    float4 a = make_float4(0.f, 0.f, 0.f, 0.f);
                    float4 bb = make_float4(0.f, 0.f, 0.f, 0.f);
                    if (idx < KSTEP * 16) {
                        int kk = idx >> 4, mm4 = (idx & 15) << 2;
                        int t_local = t0 + (p + 1) * KSTEP + kk;
                        int trow = b * TDIM + t_local;
                        int gm = m0 + mm4;
                        if (gm < NIN)
                            a = *(const float4*)&x[trow * NIN + gm];
                        else if (gm < NIN + NDIM && t_local > 0)
                            a = *(const float4*)&z[(trow - 1) * NDIM + (gm - NIN)];
                        int gn = n0 + mm4;
                        if (gn < NDIM)
                            bb = *(const float4*)&g_Yr[trow * NDIM + gn];
                    }
                    ra[r] = a; rb[r] = bb;
                }
            }
            #pragma unroll
            for (int kk = 0; kk < KSTEP; kk++) {
                float4 av = *(const float4*)&As[buf][kk][ty * 4];
                float4 bv = *(const float4*)&Bs[buf][kk][tx * 4];
                ull b01 = pk(bv.x, bv.y);
                ull b23 = pk(bv.z, bv.w);
                ull aa;
                aa = pk(av.x, av.x); fma2(acc[0][0], aa, b01); fma2(acc[0][1], aa, b23);
                aa = pk(av.y, av.y); fma2(acc[1][0], aa, b01); fma2(acc[1][1], aa, b23);
                aa = pk(av.z, av.z); fma2(acc[2][0], aa, b01); fma2(acc[2][1], aa, b23);
                aa = pk(av.w, av.w); fma2(acc[3][0], aa, b01); fma2(acc[3][1], aa, b23);
            }
            __syncthreads();
        }

        #pragma unroll
        for (int i = 0; i < 4; i++) {
            float2 p0 = upk(acc[i][0]);
            float2 p1 = upk(acc[i][1]);
            float vals[4] = {p0.x, p0.y, p1.x, p1.y};
            int gm = m0 + ty * 4 + i;
            #pragma unroll
            for (int j = 0; j < 4; j++) {
                int gn = n0 + tx * 4 + j;
                if (gn < NDIM) {
                    if (gm < NIN) {
                        atomicAdd(&out[gm * NDIM + gn], vals[j]);
                    } else if (gm < NIN + NDIM) {
                        int rr = gm - NIN;
                        if (rr != gn)  // autapse mask: diagonal stays 0
                            atomicAdd(&out[NIN * NDIM + rr * NDIM + gn], vals[j]);
                    }
                }
            }
        }
    } else {
        // dw_out tile: 64 m-rows (neurons) x 10 cols; A=z (float4), B=e1f
        const int m0 = (tile - MTILES) * 64;
        float acc[4] = {0.f, 0.f, 0.f, 0.f};

        // preload e1f for all 100 k-rows: 1000 contiguous floats -> Bs flat
        float* sB = &Bs[0][0][0];
        if (tid < 250)
            ((float4*)sB)[tid] = ((const float4*)&g_e1f[bt0 * KDIM])[tid];

        float4 ra[2];
        #pragma unroll
        for (int r = 0; r < 2; r++) {
            int idx = tid + r * 256;
            float4 a = make_float4(0.f, 0.f, 0.f, 0.f);
            if (idx < KSTEP * 16) {
                int kk = idx >> 4, mm4 = (idx & 15) << 2;
                int gm = m0 + mm4;
                if (gm < NDIM)
                    a = *(const float4*)&z[(bt0 + kk) * NDIM + gm];
            }
            ra[r] = a;
        }

        #pragma unroll
        for (int p = 0; p < 4; p++) {
            const int buf = p & 1;
            #pragma unroll
            for (int r = 0; r < 2; r++) {
                int idx = tid + r * 256;
                if (idx < KSTEP * 16) {
                    int kk = idx >> 4, mm4 = (idx & 15) << 2;
                    *(float4*)&As[buf][kk][mm4] = ra[r];
                }
            }
            __syncthreads();
            if (p < 3) {
                #pragma unroll
                for (int r = 0; r < 2; r++) {
                    int idx = tid + r * 256;
                    float4 a = make_float4(0.f, 0.f, 0.f, 0.f);
                    if (idx < KSTEP * 16) {
                        int kk = idx >> 4, mm4 = (idx & 15) << 2;
                        int gm = m0 + mm4;
                        if (gm < NDIM)
                            a = *(const float4*)&z[(bt0 + (p + 1) * KSTEP + kk) * NDIM + gm];
                    }
                    ra[r] = a;
                }
            }
            #pragma unroll
            for (int kk = 0; kk < KSTEP; kk++) {
                float4 av = *(const float4*)&As[buf][kk][ty * 4];
                float bb = sB[(p * KSTEP + kk) * KDIM + tx];  // tx>=10 garbage, unused
                acc[0] = fmaf(av.x, bb, acc[0]);
                acc[1] = fmaf(av.y, bb, acc[1]);
                acc[2] = fmaf(av.z, bb, acc[2]);
                acc[3] = fmaf(av.w, bb, acc[3]);
            }
            __syncthreads();
        }

        if (tx < KDIM) {
            #pragma unroll
            for (int i = 0; i < 4; i++) {
                int gm = m0 + ty * 4 + i;
                if (gm < NDIM)
                    atomicAdd(&out[NIN * NDIM + NDIM * NDIM + gm * KDIM + tx], acc[i]);
            }
        }
    }
}

extern "C" void kernel_launch(void* const* d_in, const int* in_sizes, int n_in,
                              void* d_out, int out_size) {
    const float* v     = (const float*)d_in[0];
    const float* z     = (const float*)d_in[1];
    const float* x     = (const float*)d_in[2];
    const float* e1    = (const float*)d_in[3];
    const float* e2    = (const float*)d_in[4];
    const float* w_out = (const float*)d_in[5];
    float* out = (float*)d_out;

    k_g2<<<106, 512>>>(v, z, e1, e2, w_out, out);
    k_gemm<<<dim3(24, 12), 256>>>(x, z, out);
}